// round 15
// baseline (speedup 1.0000x reference)
#include <cuda_runtime.h>
#include <cuda_fp16.h>
#include <cstdint>
#include <math.h>

// Problem constants (MoELayer_76433237999752)
#define TT 4096      // tokens = B*S
#define DM 1024      // d_model
#define DH 4096      // d_hidden
#define NE 8         // experts
#define RTOT (TT*2)  // total routed rows (top-2)
#define HPAD 128     // row padding so GEMM2 A-tile reads never go OOB

// GEMM tiling: CTA tile 128x128, BK=64, 256 threads = 8 warps (2x4),
// warp tile 64x32, 3-stage cp.async, 2 CTAs/SM, single-pass fp16 mma.
#define BM 128
#define BN 128
#define BK 64
#define NTHREADS 256
// SMEM stage layout (bytes): A[128 rows x 144B] B[64 rows x 272B]
#define A_OFF 0
#define B_OFF 18432
#define STAGE_BYTES 35840
#define NSTAGE 3
#define SMEM_BYTES (STAGE_BYTES * NSTAGE)   // 107520

#define W2_SLICES 8192                       // 8192 slices x 1024 float4 = full W2

// ===========================================================================
// Device-global scratch
// ===========================================================================
__device__ int    g_cnt [NE];
__device__ int    g_w2ctr;                            // W2 convert slice counter
__device__ int    g_tok [NE * TT];
__device__ float  g_wt  [NE * TT];                    // combine weight per slot
__device__ __half g_x  [(size_t)TT * DM];             // x in fp16
__device__ __half g_w1 [(size_t)NE * DM * DH];        // W1 in fp16
__device__ __half g_w2 [(size_t)NE * DH * DM];        // W2 in fp16
__device__ __half g_h  [(size_t)(RTOT + HPAD) * DH];  // hidden, fp16

// ===========================================================================
// PTX helpers (plain sm_80-era — nothing "a"-gated)
// ===========================================================================
__device__ __forceinline__ uint32_t smem_u32(const void* p) {
    uint32_t a;
    asm("{ .reg .u64 t; cvta.to.shared.u64 t, %1; cvt.u32.u64 %0, t; }" : "=r"(a) : "l"(p));
    return a;
}
__device__ __forceinline__ void ldsm_x4(uint32_t* r, uint32_t addr) {
    asm volatile("ldmatrix.sync.aligned.m8n8.x4.shared.b16 {%0,%1,%2,%3}, [%4];"
                 : "=r"(r[0]), "=r"(r[1]), "=r"(r[2]), "=r"(r[3]) : "r"(addr));
}
__device__ __forceinline__ void ldsm_x2t(uint32_t* r, uint32_t addr) {
    asm volatile("ldmatrix.sync.aligned.m8n8.x2.trans.shared.b16 {%0,%1}, [%2];"
                 : "=r"(r[0]), "=r"(r[1]) : "r"(addr));
}
__device__ __forceinline__ void mma16816(float* c, const uint32_t* a, const uint32_t* b) {
    asm volatile("mma.sync.aligned.m16n8k16.row.col.f32.f16.f16.f32 "
                 "{%0,%1,%2,%3}, {%4,%5,%6,%7}, {%8,%9}, {%0,%1,%2,%3};"
                 : "+f"(c[0]), "+f"(c[1]), "+f"(c[2]), "+f"(c[3])
                 : "r"(a[0]), "r"(a[1]), "r"(a[2]), "r"(a[3]), "r"(b[0]), "r"(b[1]));
}
__device__ __forceinline__ void cp16(uint32_t dst, const void* src, uint32_t sz) {
    asm volatile("cp.async.cg.shared.global [%0], [%1], 16, %2;"
                 :: "r"(dst), "l"(src), "r"(sz) : "memory");
}
#define CP_COMMIT() asm volatile("cp.async.commit_group;" ::: "memory")
#define CP_WAIT(n)  asm volatile("cp.async.wait_group %0;" :: "n"(n) : "memory")

// fp32x4 -> fp16x4
__device__ __forceinline__ uint2 pack4h(float4 v) {
    __half2 h0 = __float22half2_rn(make_float2(v.x, v.y));
    __half2 h1 = __float22half2_rn(make_float2(v.z, v.w));
    return make_uint2(*(uint32_t*)&h0, *(uint32_t*)&h1);
}

// ===========================================================================
// Fused prep kernel: 1024 blocks x 256 threads.
//   blocks [0,512):    gate (8 tokens/block) + x fp16 conversion + out zeroing
//   blocks [512,1024): convert W1 fp32->fp16
// g_cnt, g_w2ctr must be zeroed beforehand (memset node).
// W2 is converted inside gemm1 by EARLY-EXIT blocks only (atomic slice queue).
// ===========================================================================
#define GATE_BLKS 512
#define CONV_BLKS 512
#define CONV_N4   ((size_t)NE * DM * DH / 4)   // 8388608 float4 per weight

__global__ void __launch_bounds__(256)
prep_kernel(const float* __restrict__ x,
            const float* __restrict__ Wg,
            const float* __restrict__ bg,
            const float* __restrict__ W1,
            __half* __restrict__ w1o,
            float* __restrict__ out_y,
            float* __restrict__ logits_out,
            int write_logits) {
    int bx  = blockIdx.x;
    int tid = threadIdx.x;

    if (bx >= GATE_BLKS) {
        // ---- W1 conversion ----
        int cb = bx - GATE_BLKS;
        size_t stride = (size_t)CONV_BLKS * 256;
        for (size_t i = (size_t)cb * 256 + tid; i < CONV_N4; i += stride)
            ((uint2*)w1o)[i] = pack4h(((const float4*)W1)[i]);
        return;
    }

    // ---- gate ----
    __shared__ float s_wgT[NE][DM];   // 32 KB, transposed gate weights
    int lane = tid & 31, w = tid >> 5;

    for (int i = tid; i < DM * NE; i += 256) {
        int d = i >> 3, e = i & 7;
        s_wgT[e][d] = Wg[i];
    }
    __syncthreads();

    int t = bx * 8 + w;
    const float* xr = x + (size_t)t * DM;
    float4* orow4 = (float4*)(out_y + (size_t)t * DM);

    float acc[NE];
#pragma unroll
    for (int e = 0; e < NE; e++) acc[e] = 0.0f;

    const float4 z4 = make_float4(0.f, 0.f, 0.f, 0.f);
#pragma unroll
    for (int i = 0; i < 8; i++) {
        int d4 = i * 32 + lane;            // float4 index within row
        float4 xv = ((const float4*)xr)[d4];
        ((uint2*)(g_x + (size_t)t * DM))[d4] = pack4h(xv);
        orow4[d4] = z4;                     // zero the output row (scatter target)
#pragma unroll
        for (int e = 0; e < NE; e++) {
            float4 wv = ((const float4*)&s_wgT[e][0])[d4];
            acc[e] += xv.x * wv.x + xv.y * wv.y + xv.z * wv.z + xv.w * wv.w;
        }
    }
#pragma unroll
    for (int e = 0; e < NE; e++)
#pragma unroll
        for (int o = 16; o > 0; o >>= 1)
            acc[e] += __shfl_xor_sync(0xffffffffu, acc[e], o);

    if (lane == 0) {
#pragma unroll
        for (int e = 0; e < NE; e++) acc[e] += bg[e];
        if (write_logits)
#pragma unroll
            for (int e = 0; e < NE; e++)
                logits_out[(size_t)t * NE + e] = acc[e];
        int i0 = 0; float v0 = acc[0];
#pragma unroll
        for (int e = 1; e < NE; e++) if (acc[e] > v0) { v0 = acc[e]; i0 = e; }
        int i1 = -1; float v1 = -INFINITY;
#pragma unroll
        for (int e = 0; e < NE; e++) {
            if (e == i0) continue;
            if (acc[e] > v1) { v1 = acc[e]; i1 = e; }
        }
        float ew  = expf(v1 - v0);
        float inv = 1.0f / (1.0f + ew);

        int s0 = atomicAdd(&g_cnt[i0], 1);
        g_tok[i0 * TT + s0] = t;
        g_wt [i0 * TT + s0] = inv;
        int s1 = atomicAdd(&g_cnt[i1], 1);
        g_tok[i1 * TT + s1] = t;
        g_wt [i1 * TT + s1] = ew * inv;
    }
}

// ===========================================================================
// GEMM core: 128x128 CTA tile, BK=64, 8 warps (2x4), warp tile 64x32,
// 3-stage cp.async, single-pass fp16 mma.
// ===========================================================================
struct TilePtrs {
    const __half* a[4];          // A row pointers (4 rows per thread)
    uint32_t asz[4];             // 16 or 0 (zero-fill)
    const __half* b;             // B base (krow kr0)
    int aStep, bStep;            // elems to advance per kt
    int bRowStride;              // 16 * ldb (elems between the 4 B chunks)
    uint32_t aDst, bDst;         // smem offsets within stage (chunk 0)
};

__device__ __forceinline__ void issue_tile(uint32_t sb, int stage, const TilePtrs& tp, int kt) {
    uint32_t s = sb + stage * STAGE_BYTES;
    int ao = kt * tp.aStep;
    int bo = kt * tp.bStep;
#pragma unroll
    for (int i = 0; i < 4; i++)
        cp16(s + A_OFF + tp.aDst + i * 4608, tp.a[i] + ao, tp.asz[i]);   // 32 rows * 144B
#pragma unroll
    for (int i = 0; i < 4; i++)
        cp16(s + B_OFF + tp.bDst + i * 4352, tp.b + bo + i * tp.bRowStride, 16); // 16 rows * 272B
    CP_COMMIT();
}

template <int NC>
__device__ __forceinline__ void gemm_core(uint32_t sb, const TilePtrs& tp,
                                          float cacc[4][4][4],
                                          uint32_t aOff, uint32_t bOff) {
    issue_tile(sb, 0, tp, 0);
    issue_tile(sb, 1, tp, 1);
#pragma unroll 1
    for (int kt = 0; kt < NC; kt++) {
        if (kt + 1 < NC) { CP_WAIT(1); } else { CP_WAIT(0); }
        __syncthreads();
        if (kt + 2 < NC) issue_tile(sb, (kt + 2) % NSTAGE, tp, kt + 2);
        uint32_t s = sb + (kt % NSTAGE) * STAGE_BYTES;
#pragma unroll
        for (int k16 = 0; k16 < 4; k16++) {
            uint32_t ah[4][4];
#pragma unroll
            for (int mi = 0; mi < 4; mi++)
                ldsm_x4(ah[mi], s + A_OFF + aOff + mi * 2304 + k16 * 32);   // 16 rows*144B
#pragma unroll
            for (int ni = 0; ni < 4; ni++) {
                uint32_t bb[2];
                ldsm_x2t(bb, s + B_OFF + bOff + ni * 16 + k16 * 4352);       // 16 krows*272B
#pragma unroll
                for (int mi = 0; mi < 4; mi++) mma16816(cacc[mi][ni], ah[mi], bb);
            }
        }
    }
}

// warp layout: 8 warps as (wm, wn) = (wid>>2, wid&3); warp tile 64x32.
__device__ __forceinline__ uint32_t calc_aoff(int wm, int lane) {
    return (uint32_t)(wm * 64 + (lane & 7) + ((lane >> 3) & 1) * 8) * 144
         + (lane >> 4) * 16;
}
__device__ __forceinline__ uint32_t calc_boff(int wn, int lane) {
    return (uint32_t)(lane & 15) * 272 + wn * 64;
}

// inline exclusive prefix over g_cnt
__device__ __forceinline__ int calc_base(int e) {
    int base = 0;
#pragma unroll
    for (int i = 0; i < NE; i++)
        if (i < e) base += g_cnt[i];
    return base;
}

// ===========================================================================
// GEMM1: h[base+r] = relu( x[tok[r]] @ W1[e] + b1[e] )  (h stored fp16)
// EARLY-EXIT blocks drain the W2 convert-slice queue (1-2 slices each, 6144
// empty blocks for 8192 slices). Working blocks never touch it — zero cost
// on the MMA critical path.
// ===========================================================================
__global__ void __launch_bounds__(NTHREADS, 2)
moe_gemm1(const float* __restrict__ b1,
          const float* __restrict__ W2, __half* __restrict__ w2o) {
    __shared__ int s_slice;
    int e   = blockIdx.z;
    int cnt = g_cnt[e];
    int rb  = blockIdx.y * BM;
    int tid = threadIdx.x;

    if (rb >= cnt) {
        // early-exit block: drain W2 convert slices until queue is empty
        for (;;) {
            if (tid == 0) s_slice = atomicAdd(&g_w2ctr, 1);
            __syncthreads();
            int sl = s_slice;
            __syncthreads();
            if (sl >= W2_SLICES) return;
            size_t b0 = (size_t)sl * 1024 + tid;
#pragma unroll
            for (int i = 0; i < 4; i++)
                ((uint2*)w2o)[b0 + i * 256] = pack4h(((const float4*)W2)[b0 + i * 256]);
        }
    }

    int nb   = blockIdx.x * BN;
    int base = calc_base(e);

    extern __shared__ __align__(128) char smem[];
    uint32_t sb = smem_u32(smem);

    int lane = tid & 31, wid = tid >> 5;
    int wm = wid >> 2, wn = wid & 3;

    TilePtrs tp;
    {
        // A: 1024 16B chunks (128 rows x 8 segs), 4 per thread: rows r0+32i
        int r0 = tid >> 3, sg = tid & 7;
#pragma unroll
        for (int i = 0; i < 4; i++) {
            int r = r0 + 32 * i;
            bool v = (rb + r) < cnt;
            int tok = g_tok[e * TT + (v ? rb + r : 0)];
            tp.a[i]  = g_x + (size_t)tok * DM + sg * 8;
            tp.asz[i] = v ? 16 : 0;
        }
        tp.aDst = (uint32_t)r0 * 144 + sg * 16;
        tp.aStep = BK;
        // B: 1024 chunks (64 k-rows x 16 segs), 4 per thread: krows kr0+16i
        int kr0 = tid >> 4, bs = tid & 15;
        size_t wbase = (size_t)e * DM * DH;
        tp.b = g_w1 + wbase + (size_t)kr0 * DH + nb + bs * 8;
        tp.bDst = (uint32_t)kr0 * 272 + bs * 16;
        tp.bStep = BK * DH;
        tp.bRowStride = 16 * DH;
    }

    uint32_t aOff = calc_aoff(wm, lane);
    uint32_t bOff = calc_boff(wn, lane);

    float cacc[4][4][4];
#pragma unroll
    for (int mi = 0; mi < 4; mi++)
#pragma unroll
        for (int ni = 0; ni < 4; ni++)
#pragma unroll
            for (int q = 0; q < 4; q++) cacc[mi][ni][q] = 0.0f;

    gemm_core<DM / BK>(sb, tp, cacc, aOff, bOff);

    const float* bb = b1 + (size_t)e * DH + nb;
    int er = wm * 64 + (lane >> 2);
    int ec = wn * 32 + (lane & 3) * 2;
#pragma unroll
    for (int mi = 0; mi < 4; mi++) {
#pragma unroll
        for (int rr = 0; rr < 2; rr++) {
            int m = er + mi * 16 + rr * 8;
            if (rb + m >= cnt) continue;
            size_t rowoff = (size_t)(base + rb + m) * DH + nb;
#pragma unroll
            for (int ni = 0; ni < 4; ni++) {
                int c = ec + ni * 8;
                float v0 = cacc[mi][ni][rr * 2 + 0] + bb[c];
                float v1 = cacc[mi][ni][rr * 2 + 1] + bb[c + 1];
                v0 = v0 > 0.f ? v0 : 0.f;
                v1 = v1 > 0.f ? v1 : 0.f;
                __half2 hv = __float22half2_rn(make_float2(v0, v1));
                *(uint32_t*)(g_h + rowoff + c) = *(uint32_t*)&hv;
            }
        }
    }
}

// ===========================================================================
// GEMM2: out[tok[r]] += w[r] * ( h[base+r] @ W2[e] + b2[e] )   (atomic scatter)
// ===========================================================================
__global__ void __launch_bounds__(NTHREADS, 2)
moe_gemm2(const float* __restrict__ b2, float* __restrict__ out) {
    int e   = blockIdx.z;
    int cnt = g_cnt[e];
    int rb  = blockIdx.y * BM;
    if (rb >= cnt) return;
    int nb   = blockIdx.x * BN;
    int base = calc_base(e);

    extern __shared__ __align__(128) char smem[];
    uint32_t sb = smem_u32(smem);

    int tid  = threadIdx.x;
    int lane = tid & 31, wid = tid >> 5;
    int wm = wid >> 2, wn = wid & 3;

    TilePtrs tp;
    {
        int r0 = tid >> 3, sg = tid & 7;
#pragma unroll
        for (int i = 0; i < 4; i++) {
            int r = r0 + 32 * i;
            tp.a[i]  = g_h + (size_t)(base + rb + r) * DH + sg * 8;  // HPAD covers tails
            tp.asz[i] = 16;
        }
        tp.aDst = (uint32_t)r0 * 144 + sg * 16;
        tp.aStep = BK;
        int kr0 = tid >> 4, bs = tid & 15;
        size_t wbase = (size_t)e * DH * DM;
        tp.b = g_w2 + wbase + (size_t)kr0 * DM + nb + bs * 8;
        tp.bDst = (uint32_t)kr0 * 272 + bs * 16;
        tp.bStep = BK * DM;
        tp.bRowStride = 16 * DM;
    }

    uint32_t aOff = calc_aoff(wm, lane);
    uint32_t bOff = calc_boff(wn, lane);

    float cacc[4][4][4];
#pragma unroll
    for (int mi = 0; mi < 4; mi++)
#pragma unroll
        for (int ni = 0; ni < 4; ni++)
#pragma unroll
            for (int q = 0; q < 4; q++) cacc[mi][ni][q] = 0.0f;

    gemm_core<DH / BK>(sb, tp, cacc, aOff, bOff);

    const float* bb = b2 + (size_t)e * DM + nb;
    int er = wm * 64 + (lane >> 2);
    int ec = wn * 32 + (lane & 3) * 2;
#pragma unroll
    for (int mi = 0; mi < 4; mi++) {
#pragma unroll
        for (int rr = 0; rr < 2; rr++) {
            int m = er + mi * 16 + rr * 8;
            if (rb + m >= cnt) continue;
            int   tok = g_tok[e * TT + rb + m];
            float w   = g_wt [e * TT + rb + m];
            float* orow = out + (size_t)tok * DM + nb;
#pragma unroll
            for (int ni = 0; ni < 4; ni++) {
                int c = ec + ni * 8;
                atomicAdd(&orow[c],     w * (cacc[mi][ni][rr * 2 + 0] + bb[c]));
                atomicAdd(&orow[c + 1], w * (cacc[mi][ni][rr * 2 + 1] + bb[c + 1]));
            }
        }
    }
}

// ===========================================================================
// Launch
// ===========================================================================
extern "C" void kernel_launch(void* const* d_in, const int* in_sizes, int n_in,
                              void* d_out, int out_size) {
    const float* x  = (const float*)d_in[0];
    const float* Wg = (const float*)d_in[1];
    const float* bg = (const float*)d_in[2];
    const float* W1 = (const float*)d_in[3];
    const float* b1 = (const float*)d_in[4];
    const float* W2 = (const float*)d_in[5];
    const float* b2 = (const float*)d_in[6];

    float* out_y = (float*)d_out;
    int write_logits = (out_size >= TT * (DM + NE)) ? 1 : 0;
    float* logits = out_y + (size_t)TT * DM;

    cudaFuncSetAttribute(moe_gemm1, cudaFuncAttributeMaxDynamicSharedMemorySize, SMEM_BYTES);
    cudaFuncSetAttribute(moe_gemm2, cudaFuncAttributeMaxDynamicSharedMemorySize, SMEM_BYTES);

    __half *w1p, *w2p;
    cudaGetSymbolAddress((void**)&w1p, g_w1);
    cudaGetSymbolAddress((void**)&w2p, g_w2);
    int *cntp, *w2ctrp;
    cudaGetSymbolAddress((void**)&cntp,   g_cnt);
    cudaGetSymbolAddress((void**)&w2ctrp, g_w2ctr);

    cudaMemsetAsync(cntp,   0, NE * sizeof(int));
    cudaMemsetAsync(w2ctrp, 0, sizeof(int));

    prep_kernel<<<GATE_BLKS + CONV_BLKS, 256>>>(x, Wg, bg, W1, w1p, out_y,
                                                logits, write_logits);

    moe_gemm1<<<dim3(DH / BN, TT / BM, NE), NTHREADS, SMEM_BYTES>>>(b1, W2, w2p);
    moe_gemm2<<<dim3(DM / BN, TT / BM, NE), NTHREADS, SMEM_BYTES>>>(b2, out_y);
}

// round 16
// speedup vs baseline: 1.0539x; 1.0539x over previous
#include <cuda_runtime.h>
#include <cuda_fp16.h>
#include <cstdint>
#include <math.h>

// Problem constants (MoELayer_76433237999752)
#define TT 4096      // tokens = B*S
#define DM 1024      // d_model
#define DH 4096      // d_hidden
#define NE 8         // experts
#define RTOT (TT*2)  // total routed rows (top-2)
#define HPAD 128     // row padding so GEMM2 A-tile reads never go OOB

// GEMM tiling: CTA tile 128x128, BK=64, 256 threads = 8 warps (2x4),
// warp tile 64x32, 3-stage cp.async, 2 CTAs/SM, single-pass fp16 mma.
#define BM 128
#define BN 128
#define BK 64
#define NTHREADS 256
// SMEM stage layout (bytes): A[128 rows x 144B] B[64 rows x 272B]
#define A_OFF 0
#define B_OFF 18432
#define STAGE_BYTES 35840
#define NSTAGE 3
#define SMEM_BYTES (STAGE_BYTES * NSTAGE)   // 107520

// ===========================================================================
// Device-global scratch
// ===========================================================================
__device__ int    g_cnt [NE];
__device__ int    g_tok [NE * TT];
__device__ float  g_wt  [NE * TT];                    // combine weight per slot
__device__ __half g_x  [(size_t)TT * DM];             // x in fp16
__device__ __half g_w1 [(size_t)NE * DM * DH];        // W1 in fp16
__device__ __half g_w2 [(size_t)NE * DH * DM];        // W2 in fp16
__device__ __half g_h  [(size_t)(RTOT + HPAD) * DH];  // hidden, fp16

// ===========================================================================
// PTX helpers (plain sm_80/sm_90-era — nothing "a"-gated)
// ===========================================================================
__device__ __forceinline__ uint32_t smem_u32(const void* p) {
    uint32_t a;
    asm("{ .reg .u64 t; cvta.to.shared.u64 t, %1; cvt.u32.u64 %0, t; }" : "=r"(a) : "l"(p));
    return a;
}
__device__ __forceinline__ void ldsm_x4(uint32_t* r, uint32_t addr) {
    asm volatile("ldmatrix.sync.aligned.m8n8.x4.shared.b16 {%0,%1,%2,%3}, [%4];"
                 : "=r"(r[0]), "=r"(r[1]), "=r"(r[2]), "=r"(r[3]) : "r"(addr));
}
__device__ __forceinline__ void ldsm_x2t(uint32_t* r, uint32_t addr) {
    asm volatile("ldmatrix.sync.aligned.m8n8.x2.trans.shared.b16 {%0,%1}, [%2];"
                 : "=r"(r[0]), "=r"(r[1]) : "r"(addr));
}
__device__ __forceinline__ void mma16816(float* c, const uint32_t* a, const uint32_t* b) {
    asm volatile("mma.sync.aligned.m16n8k16.row.col.f32.f16.f16.f32 "
                 "{%0,%1,%2,%3}, {%4,%5,%6,%7}, {%8,%9}, {%0,%1,%2,%3};"
                 : "+f"(c[0]), "+f"(c[1]), "+f"(c[2]), "+f"(c[3])
                 : "r"(a[0]), "r"(a[1]), "r"(a[2]), "r"(a[3]), "r"(b[0]), "r"(b[1]));
}
__device__ __forceinline__ void cp16(uint32_t dst, const void* src, uint32_t sz) {
    asm volatile("cp.async.cg.shared.global [%0], [%1], 16, %2;"
                 :: "r"(dst), "l"(src), "r"(sz) : "memory");
}
#define CP_COMMIT() asm volatile("cp.async.commit_group;" ::: "memory")
#define CP_WAIT(n)  asm volatile("cp.async.wait_group %0;" :: "n"(n) : "memory")

// vectorized global reduction: out[0] += v0, out[1] += v1 (no return, REDG path)
__device__ __forceinline__ void redg_add_v2(float* addr, float v0, float v1) {
    asm volatile("red.global.add.v2.f32 [%0], {%1, %2};"
                 :: "l"(addr), "f"(v0), "f"(v1) : "memory");
}

// fp32x4 -> fp16x4
__device__ __forceinline__ uint2 pack4h(float4 v) {
    __half2 h0 = __float22half2_rn(make_float2(v.x, v.y));
    __half2 h1 = __float22half2_rn(make_float2(v.z, v.w));
    return make_uint2(*(uint32_t*)&h0, *(uint32_t*)&h1);
}

// ===========================================================================
// Fused prep kernel: 1024 blocks x 256 threads.
//   blocks [0,512):    gate (8 tokens/block) + x fp16 conversion + out zeroing
//   blocks [512,1024): convert W1 fp32->fp16
// g_cnt must be zeroed beforehand (memset node). W2 is converted inside gemm1.
// ===========================================================================
#define GATE_BLKS 512
#define CONV_BLKS 512
#define CONV_N4   ((size_t)NE * DM * DH / 4)   // 8388608 float4 per weight

__global__ void __launch_bounds__(256)
prep_kernel(const float* __restrict__ x,
            const float* __restrict__ Wg,
            const float* __restrict__ bg,
            const float* __restrict__ W1,
            __half* __restrict__ w1o,
            float* __restrict__ out_y,
            float* __restrict__ logits_out,
            int write_logits) {
    int bx  = blockIdx.x;
    int tid = threadIdx.x;

    if (bx >= GATE_BLKS) {
        // ---- W1 conversion ----
        int cb = bx - GATE_BLKS;
        size_t stride = (size_t)CONV_BLKS * 256;
        for (size_t i = (size_t)cb * 256 + tid; i < CONV_N4; i += stride)
            ((uint2*)w1o)[i] = pack4h(((const float4*)W1)[i]);
        return;
    }

    // ---- gate ----
    __shared__ float s_wgT[NE][DM];   // 32 KB, transposed gate weights
    int lane = tid & 31, w = tid >> 5;

    for (int i = tid; i < DM * NE; i += 256) {
        int d = i >> 3, e = i & 7;
        s_wgT[e][d] = Wg[i];
    }
    __syncthreads();

    int t = bx * 8 + w;
    const float* xr = x + (size_t)t * DM;
    float4* orow4 = (float4*)(out_y + (size_t)t * DM);

    float acc[NE];
#pragma unroll
    for (int e = 0; e < NE; e++) acc[e] = 0.0f;

    const float4 z4 = make_float4(0.f, 0.f, 0.f, 0.f);
#pragma unroll
    for (int i = 0; i < 8; i++) {
        int d4 = i * 32 + lane;            // float4 index within row
        float4 xv = ((const float4*)xr)[d4];
        ((uint2*)(g_x + (size_t)t * DM))[d4] = pack4h(xv);
        orow4[d4] = z4;                     // zero the output row (scatter target)
#pragma unroll
        for (int e = 0; e < NE; e++) {
            float4 wv = ((const float4*)&s_wgT[e][0])[d4];
            acc[e] += xv.x * wv.x + xv.y * wv.y + xv.z * wv.z + xv.w * wv.w;
        }
    }
#pragma unroll
    for (int e = 0; e < NE; e++)
#pragma unroll
        for (int o = 16; o > 0; o >>= 1)
            acc[e] += __shfl_xor_sync(0xffffffffu, acc[e], o);

    if (lane == 0) {
#pragma unroll
        for (int e = 0; e < NE; e++) acc[e] += bg[e];
        if (write_logits)
#pragma unroll
            for (int e = 0; e < NE; e++)
                logits_out[(size_t)t * NE + e] = acc[e];
        int i0 = 0; float v0 = acc[0];
#pragma unroll
        for (int e = 1; e < NE; e++) if (acc[e] > v0) { v0 = acc[e]; i0 = e; }
        int i1 = -1; float v1 = -INFINITY;
#pragma unroll
        for (int e = 0; e < NE; e++) {
            if (e == i0) continue;
            if (acc[e] > v1) { v1 = acc[e]; i1 = e; }
        }
        float ew  = expf(v1 - v0);
        float inv = 1.0f / (1.0f + ew);

        int s0 = atomicAdd(&g_cnt[i0], 1);
        g_tok[i0 * TT + s0] = t;
        g_wt [i0 * TT + s0] = inv;
        int s1 = atomicAdd(&g_cnt[i1], 1);
        g_tok[i1 * TT + s1] = t;
        g_wt [i1 * TT + s1] = ew * inv;
    }
}

// ===========================================================================
// GEMM core: 128x128 CTA tile, BK=64, 8 warps (2x4), warp tile 64x32,
// 3-stage cp.async, single-pass fp16 mma.
// ===========================================================================
struct TilePtrs {
    const __half* a[4];          // A row pointers (4 rows per thread)
    uint32_t asz[4];             // 16 or 0 (zero-fill)
    const __half* b;             // B base (krow kr0)
    int aStep, bStep;            // elems to advance per kt
    int bRowStride;              // 16 * ldb (elems between the 4 B chunks)
    uint32_t aDst, bDst;         // smem offsets within stage (chunk 0)
};

__device__ __forceinline__ void issue_tile(uint32_t sb, int stage, const TilePtrs& tp, int kt) {
    uint32_t s = sb + stage * STAGE_BYTES;
    int ao = kt * tp.aStep;
    int bo = kt * tp.bStep;
#pragma unroll
    for (int i = 0; i < 4; i++)
        cp16(s + A_OFF + tp.aDst + i * 4608, tp.a[i] + ao, tp.asz[i]);   // 32 rows * 144B
#pragma unroll
    for (int i = 0; i < 4; i++)
        cp16(s + B_OFF + tp.bDst + i * 4352, tp.b + bo + i * tp.bRowStride, 16); // 16 rows * 272B
    CP_COMMIT();
}

template <int NC>
__device__ __forceinline__ void gemm_core(uint32_t sb, const TilePtrs& tp,
                                          float cacc[4][4][4],
                                          uint32_t aOff, uint32_t bOff) {
    issue_tile(sb, 0, tp, 0);
    issue_tile(sb, 1, tp, 1);
#pragma unroll 1
    for (int kt = 0; kt < NC; kt++) {
        if (kt + 1 < NC) { CP_WAIT(1); } else { CP_WAIT(0); }
        __syncthreads();
        if (kt + 2 < NC) issue_tile(sb, (kt + 2) % NSTAGE, tp, kt + 2);
        uint32_t s = sb + (kt % NSTAGE) * STAGE_BYTES;
#pragma unroll
        for (int k16 = 0; k16 < 4; k16++) {
            uint32_t ah[4][4];
#pragma unroll
            for (int mi = 0; mi < 4; mi++)
                ldsm_x4(ah[mi], s + A_OFF + aOff + mi * 2304 + k16 * 32);   // 16 rows*144B
#pragma unroll
            for (int ni = 0; ni < 4; ni++) {
                uint32_t bb[2];
                ldsm_x2t(bb, s + B_OFF + bOff + ni * 16 + k16 * 4352);       // 16 krows*272B
#pragma unroll
                for (int mi = 0; mi < 4; mi++) mma16816(cacc[mi][ni], ah[mi], bb);
            }
        }
    }
}

// warp layout: 8 warps as (wm, wn) = (wid>>2, wid&3); warp tile 64x32.
__device__ __forceinline__ uint32_t calc_aoff(int wm, int lane) {
    return (uint32_t)(wm * 64 + (lane & 7) + ((lane >> 3) & 1) * 8) * 144
         + (lane >> 4) * 16;
}
__device__ __forceinline__ uint32_t calc_boff(int wn, int lane) {
    return (uint32_t)(lane & 15) * 272 + wn * 64;
}

// inline exclusive prefix over g_cnt
__device__ __forceinline__ int calc_base(int e) {
    int base = 0;
#pragma unroll
    for (int i = 0; i < NE; i++)
        if (i < e) base += g_cnt[i];
    return base;
}

// W2 convert slice: each gemm1 block (8192 total) converts 1024 float4.
__device__ __forceinline__ void convert_w2_slice(const float* __restrict__ W2,
                                                 __half* __restrict__ w2o,
                                                 int tid) {
    size_t cbid = ((size_t)blockIdx.z * gridDim.y + blockIdx.y) * gridDim.x
                + blockIdx.x;
    size_t b0 = cbid * 1024 + tid;          // 8192 blocks * 1024 = CONV_N4
#pragma unroll
    for (int i = 0; i < 4; i++)
        ((uint2*)w2o)[b0 + i * 256] = pack4h(((const float4*)W2)[b0 + i * 256]);
}

// ===========================================================================
// GEMM1: h[base+r] = relu( x[tok[r]] @ W1[e] + b1[e] )  (h stored fp16)
// Every block also converts a static slice of W2 (early-exit blocks:
// immediately; working blocks: after their epilogue).
// ===========================================================================
__global__ void __launch_bounds__(NTHREADS, 2)
moe_gemm1(const float* __restrict__ b1,
          const float* __restrict__ W2, __half* __restrict__ w2o) {
    int e   = blockIdx.z;
    int cnt = g_cnt[e];
    int rb  = blockIdx.y * BM;
    int tid = threadIdx.x;

    if (rb >= cnt) {                       // early-exit block: just convert
        convert_w2_slice(W2, w2o, tid);
        return;
    }
    int nb   = blockIdx.x * BN;
    int base = calc_base(e);

    extern __shared__ __align__(128) char smem[];
    uint32_t sb = smem_u32(smem);

    int lane = tid & 31, wid = tid >> 5;
    int wm = wid >> 2, wn = wid & 3;

    TilePtrs tp;
    {
        // A: 1024 16B chunks (128 rows x 8 segs), 4 per thread: rows r0+32i
        int r0 = tid >> 3, sg = tid & 7;
#pragma unroll
        for (int i = 0; i < 4; i++) {
            int r = r0 + 32 * i;
            bool v = (rb + r) < cnt;
            int tok = g_tok[e * TT + (v ? rb + r : 0)];
            tp.a[i]  = g_x + (size_t)tok * DM + sg * 8;
            tp.asz[i] = v ? 16 : 0;
        }
        tp.aDst = (uint32_t)r0 * 144 + sg * 16;
        tp.aStep = BK;
        // B: 1024 chunks (64 k-rows x 16 segs), 4 per thread: krows kr0+16i
        int kr0 = tid >> 4, bs = tid & 15;
        size_t wbase = (size_t)e * DM * DH;
        tp.b = g_w1 + wbase + (size_t)kr0 * DH + nb + bs * 8;
        tp.bDst = (uint32_t)kr0 * 272 + bs * 16;
        tp.bStep = BK * DH;
        tp.bRowStride = 16 * DH;
    }

    uint32_t aOff = calc_aoff(wm, lane);
    uint32_t bOff = calc_boff(wn, lane);

    float cacc[4][4][4];
#pragma unroll
    for (int mi = 0; mi < 4; mi++)
#pragma unroll
        for (int ni = 0; ni < 4; ni++)
#pragma unroll
            for (int q = 0; q < 4; q++) cacc[mi][ni][q] = 0.0f;

    gemm_core<DM / BK>(sb, tp, cacc, aOff, bOff);

    const float* bb = b1 + (size_t)e * DH + nb;
    int er = wm * 64 + (lane >> 2);
    int ec = wn * 32 + (lane & 3) * 2;
#pragma unroll
    for (int mi = 0; mi < 4; mi++) {
#pragma unroll
        for (int rr = 0; rr < 2; rr++) {
            int m = er + mi * 16 + rr * 8;
            if (rb + m >= cnt) continue;
            size_t rowoff = (size_t)(base + rb + m) * DH + nb;
#pragma unroll
            for (int ni = 0; ni < 4; ni++) {
                int c = ec + ni * 8;
                float v0 = cacc[mi][ni][rr * 2 + 0] + bb[c];
                float v1 = cacc[mi][ni][rr * 2 + 1] + bb[c + 1];
                v0 = v0 > 0.f ? v0 : 0.f;
                v1 = v1 > 0.f ? v1 : 0.f;
                __half2 hv = __float22half2_rn(make_float2(v0, v1));
                *(uint32_t*)(g_h + rowoff + c) = *(uint32_t*)&hv;
            }
        }
    }

    convert_w2_slice(W2, w2o, tid);        // working block: convert at the end
}

// ===========================================================================
// GEMM2: out[tok[r]] += w[r] * ( h[base+r] @ W2[e] + b2[e] )
// (vectorized red.global.v2.f32 scatter)
// ===========================================================================
__global__ void __launch_bounds__(NTHREADS, 2)
moe_gemm2(const float* __restrict__ b2, float* __restrict__ out) {
    int e   = blockIdx.z;
    int cnt = g_cnt[e];
    int rb  = blockIdx.y * BM;
    if (rb >= cnt) return;
    int nb   = blockIdx.x * BN;
    int base = calc_base(e);

    extern __shared__ __align__(128) char smem[];
    uint32_t sb = smem_u32(smem);

    int tid  = threadIdx.x;
    int lane = tid & 31, wid = tid >> 5;
    int wm = wid >> 2, wn = wid & 3;

    TilePtrs tp;
    {
        int r0 = tid >> 3, sg = tid & 7;
#pragma unroll
        for (int i = 0; i < 4; i++) {
            int r = r0 + 32 * i;
            tp.a[i]  = g_h + (size_t)(base + rb + r) * DH + sg * 8;  // HPAD covers tails
            tp.asz[i] = 16;
        }
        tp.aDst = (uint32_t)r0 * 144 + sg * 16;
        tp.aStep = BK;
        int kr0 = tid >> 4, bs = tid & 15;
        size_t wbase = (size_t)e * DH * DM;
        tp.b = g_w2 + wbase + (size_t)kr0 * DM + nb + bs * 8;
        tp.bDst = (uint32_t)kr0 * 272 + bs * 16;
        tp.bStep = BK * DM;
        tp.bRowStride = 16 * DM;
    }

    uint32_t aOff = calc_aoff(wm, lane);
    uint32_t bOff = calc_boff(wn, lane);

    float cacc[4][4][4];
#pragma unroll
    for (int mi = 0; mi < 4; mi++)
#pragma unroll
        for (int ni = 0; ni < 4; ni++)
#pragma unroll
            for (int q = 0; q < 4; q++) cacc[mi][ni][q] = 0.0f;

    gemm_core<DH / BK>(sb, tp, cacc, aOff, bOff);

    const float* bb = b2 + (size_t)e * DM + nb;
    int er = wm * 64 + (lane >> 2);
    int ec = wn * 32 + (lane & 3) * 2;
#pragma unroll
    for (int mi = 0; mi < 4; mi++) {
#pragma unroll
        for (int rr = 0; rr < 2; rr++) {
            int m = er + mi * 16 + rr * 8;
            if (rb + m >= cnt) continue;
            int   tok = g_tok[e * TT + rb + m];
            float w   = g_wt [e * TT + rb + m];
            float* orow = out + (size_t)tok * DM + nb;
#pragma unroll
            for (int ni = 0; ni < 4; ni++) {
                int c = ec + ni * 8;   // 8-byte aligned (c even)
                redg_add_v2(&orow[c],
                            w * (cacc[mi][ni][rr * 2 + 0] + bb[c]),
                            w * (cacc[mi][ni][rr * 2 + 1] + bb[c + 1]));
            }
        }
    }
}

// ===========================================================================
// Launch
// ===========================================================================
extern "C" void kernel_launch(void* const* d_in, const int* in_sizes, int n_in,
                              void* d_out, int out_size) {
    const float* x  = (const float*)d_in[0];
    const float* Wg = (const float*)d_in[1];
    const float* bg = (const float*)d_in[2];
    const float* W1 = (const float*)d_in[3];
    const float* b1 = (const float*)d_in[4];
    const float* W2 = (const float*)d_in[5];
    const float* b2 = (const float*)d_in[6];

    float* out_y = (float*)d_out;
    int write_logits = (out_size >= TT * (DM + NE)) ? 1 : 0;
    float* logits = out_y + (size_t)TT * DM;

    cudaFuncSetAttribute(moe_gemm1, cudaFuncAttributeMaxDynamicSharedMemorySize, SMEM_BYTES);
    cudaFuncSetAttribute(moe_gemm2, cudaFuncAttributeMaxDynamicSharedMemorySize, SMEM_BYTES);

    __half *w1p, *w2p;
    cudaGetSymbolAddress((void**)&w1p, g_w1);
    cudaGetSymbolAddress((void**)&w2p, g_w2);
    int* cntp;
    cudaGetSymbolAddress((void**)&cntp, g_cnt);

    cudaMemsetAsync(cntp, 0, NE * sizeof(int));

    prep_kernel<<<GATE_BLKS + CONV_BLKS, 256>>>(x, Wg, bg, W1, w1p, out_y,
                                                logits, write_logits);

    moe_gemm1<<<dim3(DH / BN, TT / BM, NE), NTHREADS, SMEM_BYTES>>>(b1, W2, w2p);
    moe_gemm2<<<dim3(DM / BN, TT / BM, NE), NTHREADS, SMEM_BYTES>>>(b2, out_y);
}